// round 1
// baseline (speedup 1.0000x reference)
#include <cuda_runtime.h>
#include <math.h>

// ---------------- problem constants ----------------
constexpr int NU = 100000, NM = 20000;
constexpr int FU = 32, FM = 128;
constexpr int H1 = 8, C1 = 16, D1 = 128;   // layer 1
constexpr int H2 = 4, C2 = 128, D2 = 512;  // layer 2
constexpr int E = 250000, EL = 200000;
constexpr int HID = 16;

// ---------------- device scratch (static; no allocs allowed) ----------------
__device__ float g_hs1um[(size_t)NU * D1];
__device__ float g_hs1mu[(size_t)NM * D1];
__device__ float g_hs2um[(size_t)NU * D2];
__device__ float g_hs2mu[(size_t)NM * D2];
__device__ float g_zu[(size_t)NU * D1];
__device__ float g_zm[(size_t)NM * D1];
__device__ float g_zu2[(size_t)NU * D2];
__device__ float g_zm2[(size_t)NM * D2];
__device__ float g_es[(size_t)NU * H1];
__device__ float g_ed[(size_t)NU * H1];
__device__ float g_mbuf[(size_t)NU * H1];
__device__ float g_sbuf[(size_t)NU * H1];
__device__ float g_ex[(size_t)E * H1];
__device__ float g_wa[FM * H1];

// ---------------- helpers ----------------
static inline int ceil_div(int a, int b) { return (a + b - 1) / b; }

__device__ __forceinline__ void atomicMaxF(float* addr, float v) {
    // monotonic int trick; works with 0xFFFFFFFF (NaN) initialization
    if (signbit(v)) atomicMin((unsigned int*)addr, __float_as_uint(v));
    else            atomicMax((int*)addr, __float_as_int(v));
}

// ---------------- fold Wd @ a_d  ->  wa[K,H] ----------------
__global__ void fold_wd_k(const float* __restrict__ Wd, const float* __restrict__ a,
                          float* __restrict__ wa, int K, int H, int C) {
    int t = blockIdx.x * blockDim.x + threadIdx.x;
    if (t >= K * H) return;
    int k = t / H, h = t - k * H;
    float s = 0.f;
    for (int c = 0; c < C; c++) s += Wd[(size_t)k * H * C + h * C + c] * a[h * C + c];
    wa[t] = s;
}

// ---------------- fp32 SIMT GEMM: C[M,N] = A[M,K] @ B[K,N] ----------------
// BM=BN=128, BK=8, 256 threads, 8x8 per-thread micro-tile.
// Requires N % 128 == 0, K % 8 == 0 (true for all uses). M arbitrary.
__global__ void sgemm_k(const float* __restrict__ A, const float* __restrict__ B,
                        float* __restrict__ C, int M, int N, int K) {
    __shared__ float As[8][128];
    __shared__ float Bs[8][128];
    int t  = threadIdx.x;
    int tx = t & 15, ty = t >> 4;
    int row0 = blockIdx.y * 128, col0 = blockIdx.x * 128;
    float acc[8][8] = {};
    for (int k0 = 0; k0 < K; k0 += 8) {
        {   // A tile: 128 rows x 8 k, as float4 (2 per row)
            int m = t >> 1, k4 = (t & 1) * 4;
            int r = row0 + m;
            float4 v = make_float4(0.f, 0.f, 0.f, 0.f);
            if (r < M) v = *(const float4*)&A[(size_t)r * K + k0 + k4];
            As[k4 + 0][m] = v.x; As[k4 + 1][m] = v.y;
            As[k4 + 2][m] = v.z; As[k4 + 3][m] = v.w;
        }
        {   // B tile: 8 k x 128 n
            int kk = t >> 5, n4 = (t & 31) * 4;
            *(float4*)&Bs[kk][n4] = *(const float4*)&B[(size_t)(k0 + kk) * N + col0 + n4];
        }
        __syncthreads();
#pragma unroll
        for (int kk = 0; kk < 8; kk++) {
            float a_[8], b_[8];
            *(float4*)&a_[0] = *(const float4*)&As[kk][ty * 8];
            *(float4*)&a_[4] = *(const float4*)&As[kk][ty * 8 + 4];
            *(float4*)&b_[0] = *(const float4*)&Bs[kk][tx * 8];
            *(float4*)&b_[4] = *(const float4*)&Bs[kk][tx * 8 + 4];
#pragma unroll
            for (int i = 0; i < 8; i++)
#pragma unroll
                for (int j = 0; j < 8; j++) acc[i][j] += a_[i] * b_[j];
        }
        __syncthreads();
    }
    for (int i = 0; i < 8; i++) {
        int r = row0 + ty * 8 + i;
        if (r >= M) break;
#pragma unroll
        for (int j4 = 0; j4 < 8; j4 += 4) {
            float4 v = make_float4(acc[i][j4], acc[i][j4 + 1], acc[i][j4 + 2], acc[i][j4 + 3]);
            *(float4*)&C[(size_t)r * N + col0 + tx * 8 + j4] = v;
        }
    }
}

// ---------------- per-node attention scores ----------------
// es[n,h] = sum_c hs[n, h*C+c] * a[h,c]
__global__ void src_scores_k(const float* __restrict__ hs, const float* __restrict__ a,
                             float* __restrict__ es, int n, int H, int C) {
    int t = blockIdx.x * blockDim.x + threadIdx.x;
    if (t >= n * H) return;
    int i = t / H, h = t - i * H;
    const float* row = hs + (size_t)i * H * C + h * C;
    const float* av  = a + h * C;
    float s = 0.f;
    for (int c = 0; c < C; c++) s += row[c] * av[c];
    es[t] = s;
}

// ed[n,h] = sum_k x[n,k] * wa[k,h]
__global__ void dst_scores_k(const float* __restrict__ x, const float* __restrict__ wa,
                             float* __restrict__ ed, int n, int K, int H) {
    int t = blockIdx.x * blockDim.x + threadIdx.x;
    if (t >= n * H) return;
    int i = t / H, h = t - i * H;
    const float* row = x + (size_t)i * K;
    float s = 0.f;
    for (int k = 0; k < K; k++) s += row[k] * wa[k * H + h];
    ed[t] = s;
}

// ---------------- edge softmax passes ----------------
__global__ void edge_score_max_k(const int* __restrict__ src, const int* __restrict__ dst,
                                 const float* __restrict__ es, const float* __restrict__ ed,
                                 float* __restrict__ eo, float* __restrict__ m, int ne, int H) {
    int t = blockIdx.x * blockDim.x + threadIdx.x;
    if (t >= ne * H) return;
    int e = t / H, h = t - e * H;
    int sd = dst[e];
    float v = es[src[e] * H + h] + ed[sd * H + h];
    v = v > 0.f ? v : 0.2f * v;   // leaky_relu(0.2)
    eo[t] = v;
    atomicMaxF(&m[sd * H + h], v);
}

__global__ void edge_expsum_k(const int* __restrict__ dst, float* __restrict__ eo,
                              const float* __restrict__ m, float* __restrict__ s, int ne, int H) {
    int t = blockIdx.x * blockDim.x + threadIdx.x;
    if (t >= ne * H) return;
    int e = t / H, h = t - e * H;
    int d = dst[e];
    float ex = expf(eo[t] - m[d * H + h]);
    eo[t] = ex;
    atomicAdd(&s[d * H + h], ex);
}

// out[dst, :] += hs[src, :] * alpha[h]   (float4 granularity)
__global__ void edge_aggr_k(const int* __restrict__ src, const int* __restrict__ dst,
                            const float* __restrict__ eo, const float* __restrict__ s,
                            const float* __restrict__ hs, float* __restrict__ out,
                            int ne, int H, int C) {
    int C4 = C >> 2;
    int D4 = H * C4;
    int t = blockIdx.x * blockDim.x + threadIdx.x;
    if (t >= ne * D4) return;
    int e = t / D4, q = t - e * D4;
    int h = q / C4;
    int sd = dst[e];
    float alpha = eo[e * H + h] / (s[sd * H + h] + 1e-16f);
    float4 v = *(const float4*)&hs[(size_t)src[e] * (D4 * 4) + q * 4];
    float* o = &out[(size_t)sd * (D4 * 4) + q * 4];
#if __CUDA_ARCH__ >= 900
    atomicAdd((float4*)o, make_float4(v.x * alpha, v.y * alpha, v.z * alpha, v.w * alpha));
#else
    atomicAdd(o + 0, v.x * alpha);
    atomicAdd(o + 1, v.y * alpha);
    atomicAdd(o + 2, v.z * alpha);
    atomicAdd(o + 3, v.w * alpha);
#endif
}

// ---------------- bias (+ optional relu), in place ----------------
__global__ void bias_act_k(float* __restrict__ z, const float* __restrict__ b,
                           int n, int D, int relu) {
    int D4 = D >> 2;
    int t = blockIdx.x * blockDim.x + threadIdx.x;
    if (t >= n * D4) return;
    int q = t % D4;
    float4 v = *(float4*)&z[(size_t)t * 4];
    float4 bb = *(const float4*)&b[q * 4];
    v.x += bb.x; v.y += bb.y; v.z += bb.z; v.w += bb.w;
    if (relu) {
        v.x = fmaxf(v.x, 0.f); v.y = fmaxf(v.y, 0.f);
        v.z = fmaxf(v.z, 0.f); v.w = fmaxf(v.w, 0.f);
    }
    *(float4*)&z[(size_t)t * 4] = v;
}

// ---------------- edge decoder ----------------
// out[e] = relu(concat(zu2[lab_u[e]], zm2[lab_m[e]]) @ dw1 + db1) @ dw2 + db2
// Gathered-A GEMM: block = 128 edges x 16 hidden, K=1024 in chunks of 32.
// Thread (tx,ty): tx = hidden channel, ty*8..+7 = edge rows. Epilogue fused.
__global__ void dec_gemm_k(const float* __restrict__ zu2, const float* __restrict__ zm2,
                           const int* __restrict__ lu, const int* __restrict__ lm,
                           const float* __restrict__ dw1, const float* __restrict__ db1,
                           const float* __restrict__ dw2, const float* __restrict__ db2,
                           float* __restrict__ out, int M) {
    __shared__ float As[32][129];  // pad 129 -> conflict-free scatter stores
    __shared__ float Bs[32][16];
    int t  = threadIdx.x;
    int tx = t & 15, ty = t >> 4;
    int row0 = blockIdx.x * 128;
    float acc[8] = {};
    for (int k0 = 0; k0 < 2 * D2; k0 += 32) {
        // stage A: 128 rows x 32 k  (1024 float4, 4 per thread), gathered
#pragma unroll
        for (int l = 0; l < 4; l++) {
            int i = t + l * 256;
            int row = i >> 3, k4 = (i & 7) * 4;
            int r = row0 + row;
            float4 v = make_float4(0.f, 0.f, 0.f, 0.f);
            if (r < M) {
                int kk = k0 + k4;
                const float* base = (kk < D2) ? (zu2 + (size_t)lu[r] * D2 + kk)
                                              : (zm2 + (size_t)lm[r] * D2 + (kk - D2));
                v = *(const float4*)base;
            }
            As[k4 + 0][row] = v.x; As[k4 + 1][row] = v.y;
            As[k4 + 2][row] = v.z; As[k4 + 3][row] = v.w;
        }
        // stage B: 32 k x 16 j
        if (t < 128) {
            int kk = t >> 2, j4 = (t & 3) * 4;
            *(float4*)&Bs[kk][j4] = *(const float4*)&dw1[(size_t)(k0 + kk) * HID + j4];
        }
        __syncthreads();
#pragma unroll
        for (int kk = 0; kk < 32; kk++) {
            float b = Bs[kk][tx];
            const float* arow = &As[kk][ty * 8];
#pragma unroll
            for (int i = 0; i < 8; i++) acc[i] += arow[i] * b;
        }
        __syncthreads();
    }
    // fused epilogue: h = relu(acc + db1[tx]); out = sum_tx h * dw2[tx] + db2
    float db1v = db1[tx];
    float dw2v = dw2[tx];
    float b2   = db2[0];
#pragma unroll
    for (int i = 0; i < 8; i++) {
        float h = fmaxf(acc[i] + db1v, 0.f);
        float term = h * dw2v;
        term += __shfl_xor_sync(0xffffffffu, term, 1);
        term += __shfl_xor_sync(0xffffffffu, term, 2);
        term += __shfl_xor_sync(0xffffffffu, term, 4);
        term += __shfl_xor_sync(0xffffffffu, term, 8);
        if (tx == 0) {
            int r = row0 + ty * 8 + i;
            if (r < M) out[r] = term + b2;
        }
    }
}

// ---------------- launch ----------------
extern "C" void kernel_launch(void* const* d_in, const int* in_sizes, int n_in,
                              void* d_out, int out_size) {
    const float* xu     = (const float*)d_in[0];
    const float* xm     = (const float*)d_in[1];
    const int*   um_src = (const int*)d_in[2];
    const int*   um_dst = (const int*)d_in[3];
    const int*   mu_src = (const int*)d_in[4];
    const int*   mu_dst = (const int*)d_in[5];
    const int*   lab_u  = (const int*)d_in[6];
    const int*   lab_m  = (const int*)d_in[7];
    const float* w1um_s = (const float*)d_in[8];
    const float* w1um_d = (const float*)d_in[9];
    const float* a1um_s = (const float*)d_in[10];
    const float* a1um_d = (const float*)d_in[11];
    const float* b1um   = (const float*)d_in[12];
    const float* w1mu_s = (const float*)d_in[13];
    const float* w1mu_d = (const float*)d_in[14];
    const float* a1mu_s = (const float*)d_in[15];
    const float* a1mu_d = (const float*)d_in[16];
    const float* b1mu   = (const float*)d_in[17];
    const float* w2um_s = (const float*)d_in[18];
    const float* w2um_d = (const float*)d_in[19];
    const float* a2um_s = (const float*)d_in[20];
    const float* a2um_d = (const float*)d_in[21];
    const float* b2um   = (const float*)d_in[22];
    const float* w2mu_s = (const float*)d_in[23];
    const float* w2mu_d = (const float*)d_in[24];
    const float* a2mu_s = (const float*)d_in[25];
    const float* a2mu_d = (const float*)d_in[26];
    const float* b2mu   = (const float*)d_in[27];
    const float* dw1    = (const float*)d_in[28];
    const float* db1    = (const float*)d_in[29];
    const float* dw2    = (const float*)d_in[30];
    const float* db2    = (const float*)d_in[31];
    float* out = (float*)d_out;

    float *hs1um, *hs1mu, *hs2um, *hs2mu, *zu, *zm, *zu2, *zm2, *es, *ed, *mm, *ss, *ex, *wa;
    cudaGetSymbolAddress((void**)&hs1um, g_hs1um);
    cudaGetSymbolAddress((void**)&hs1mu, g_hs1mu);
    cudaGetSymbolAddress((void**)&hs2um, g_hs2um);
    cudaGetSymbolAddress((void**)&hs2mu, g_hs2mu);
    cudaGetSymbolAddress((void**)&zu,  g_zu);
    cudaGetSymbolAddress((void**)&zm,  g_zm);
    cudaGetSymbolAddress((void**)&zu2, g_zu2);
    cudaGetSymbolAddress((void**)&zm2, g_zm2);
    cudaGetSymbolAddress((void**)&es,  g_es);
    cudaGetSymbolAddress((void**)&ed,  g_ed);
    cudaGetSymbolAddress((void**)&mm,  g_mbuf);
    cudaGetSymbolAddress((void**)&ss,  g_sbuf);
    cudaGetSymbolAddress((void**)&ex,  g_ex);
    cudaGetSymbolAddress((void**)&wa,  g_wa);

    const int TB = 256;

    // ================= layer 1, user -> movie =================
    sgemm_k<<<dim3(D1 / 128, ceil_div(NU, 128)), 256>>>(xu, w1um_s, hs1um, NU, D1, FU);
    src_scores_k<<<ceil_div(NU * H1, TB), TB>>>(hs1um, a1um_s, es, NU, H1, C1);
    fold_wd_k<<<ceil_div(FM * H1, TB), TB>>>(w1um_d, a1um_d, wa, FM, H1, C1);
    dst_scores_k<<<ceil_div(NM * H1, TB), TB>>>(xm, wa, ed, NM, FM, H1);
    cudaMemsetAsync(mm, 0xFF, (size_t)NM * H1 * sizeof(float));
    cudaMemsetAsync(ss, 0, (size_t)NM * H1 * sizeof(float));
    cudaMemsetAsync(zm, 0, (size_t)NM * D1 * sizeof(float));
    edge_score_max_k<<<ceil_div(E * H1, TB), TB>>>(um_src, um_dst, es, ed, ex, mm, E, H1);
    edge_expsum_k<<<ceil_div(E * H1, TB), TB>>>(um_dst, ex, mm, ss, E, H1);
    edge_aggr_k<<<ceil_div(E * (D1 / 4), TB), TB>>>(um_src, um_dst, ex, ss, hs1um, zm, E, H1, C1);
    bias_act_k<<<ceil_div(NM * D1 / 4, TB), TB>>>(zm, b1um, NM, D1, 1);

    // ================= layer 1, movie -> user =================
    sgemm_k<<<dim3(D1 / 128, ceil_div(NM, 128)), 256>>>(xm, w1mu_s, hs1mu, NM, D1, FM);
    src_scores_k<<<ceil_div(NM * H1, TB), TB>>>(hs1mu, a1mu_s, es, NM, H1, C1);
    fold_wd_k<<<ceil_div(FU * H1, TB), TB>>>(w1mu_d, a1mu_d, wa, FU, H1, C1);
    dst_scores_k<<<ceil_div(NU * H1, TB), TB>>>(xu, wa, ed, NU, FU, H1);
    cudaMemsetAsync(mm, 0xFF, (size_t)NU * H1 * sizeof(float));
    cudaMemsetAsync(ss, 0, (size_t)NU * H1 * sizeof(float));
    cudaMemsetAsync(zu, 0, (size_t)NU * D1 * sizeof(float));
    edge_score_max_k<<<ceil_div(E * H1, TB), TB>>>(mu_src, mu_dst, es, ed, ex, mm, E, H1);
    edge_expsum_k<<<ceil_div(E * H1, TB), TB>>>(mu_dst, ex, mm, ss, E, H1);
    edge_aggr_k<<<ceil_div(E * (D1 / 4), TB), TB>>>(mu_src, mu_dst, ex, ss, hs1mu, zu, E, H1, C1);
    bias_act_k<<<ceil_div(NU * D1 / 4, TB), TB>>>(zu, b1mu, NU, D1, 1);

    // ================= layer 2, user -> movie (src=zu, dst=zm) =================
    sgemm_k<<<dim3(D2 / 128, ceil_div(NU, 128)), 256>>>(zu, w2um_s, hs2um, NU, D2, D1);
    src_scores_k<<<ceil_div(NU * H2, TB), TB>>>(hs2um, a2um_s, es, NU, H2, C2);
    fold_wd_k<<<ceil_div(D1 * H2, TB), TB>>>(w2um_d, a2um_d, wa, D1, H2, C2);
    dst_scores_k<<<ceil_div(NM * H2, TB), TB>>>(zm, wa, ed, NM, D1, H2);
    cudaMemsetAsync(mm, 0xFF, (size_t)NM * H2 * sizeof(float));
    cudaMemsetAsync(ss, 0, (size_t)NM * H2 * sizeof(float));
    cudaMemsetAsync(zm2, 0, (size_t)NM * D2 * sizeof(float));
    edge_score_max_k<<<ceil_div(E * H2, TB), TB>>>(um_src, um_dst, es, ed, ex, mm, E, H2);
    edge_expsum_k<<<ceil_div(E * H2, TB), TB>>>(um_dst, ex, mm, ss, E, H2);
    edge_aggr_k<<<ceil_div(E * (D2 / 4), TB), TB>>>(um_src, um_dst, ex, ss, hs2um, zm2, E, H2, C2);
    bias_act_k<<<ceil_div(NM * D2 / 4, TB), TB>>>(zm2, b2um, NM, D2, 0);

    // ================= layer 2, movie -> user (src=zm, dst=zu) =================
    sgemm_k<<<dim3(D2 / 128, ceil_div(NM, 128)), 256>>>(zm, w2mu_s, hs2mu, NM, D2, D1);
    src_scores_k<<<ceil_div(NM * H2, TB), TB>>>(hs2mu, a2mu_s, es, NM, H2, C2);
    fold_wd_k<<<ceil_div(D1 * H2, TB), TB>>>(w2mu_d, a2mu_d, wa, D1, H2, C2);
    dst_scores_k<<<ceil_div(NU * H2, TB), TB>>>(zu, wa, ed, NU, D1, H2);
    cudaMemsetAsync(mm, 0xFF, (size_t)NU * H2 * sizeof(float));
    cudaMemsetAsync(ss, 0, (size_t)NU * H2 * sizeof(float));
    cudaMemsetAsync(zu2, 0, (size_t)NU * D2 * sizeof(float));
    edge_score_max_k<<<ceil_div(E * H2, TB), TB>>>(mu_src, mu_dst, es, ed, ex, mm, E, H2);
    edge_expsum_k<<<ceil_div(E * H2, TB), TB>>>(mu_dst, ex, mm, ss, E, H2);
    edge_aggr_k<<<ceil_div(E * (D2 / 4), TB), TB>>>(mu_src, mu_dst, ex, ss, hs2mu, zu2, E, H2, C2);
    bias_act_k<<<ceil_div(NU * D2 / 4, TB), TB>>>(zu2, b2mu, NU, D2, 0);

    // ================= decoder =================
    dec_gemm_k<<<ceil_div(EL, 128), 256>>>(zu2, zm2, lab_u, lab_m, dw1, db1, dw2, db2, out, EL);
}

// round 2
// speedup vs baseline: 1.3774x; 1.3774x over previous
#include <cuda_runtime.h>
#include <math.h>

// ---------------- problem constants ----------------
constexpr int NU = 100000, NM = 20000;
constexpr int FU = 32, FM = 128;
constexpr int H1 = 8, C1 = 16, D1 = 128;   // layer 1
constexpr int H2 = 4, C2 = 128, D2 = 512;  // layer 2
constexpr int E = 250000, EL = 200000;
constexpr int HID = 16;

// ---------------- device scratch (static; no allocs allowed) ----------------
__device__ float g_hs1um[(size_t)NU * D1];
__device__ float g_hs1mu[(size_t)NM * D1];
__device__ float g_hs2mu[(size_t)NM * D2];
__device__ float g_agg[(size_t)NM * D2];     // aggregate-first buffer (layer2 um)
__device__ float g_zu[(size_t)NU * D1];
__device__ float g_zm[(size_t)NM * D1];
__device__ float g_zu2[(size_t)NU * D2];
__device__ float g_zm2[(size_t)NM * D2];
__device__ float g_es[(size_t)NU * H1];
__device__ float g_ed[(size_t)NU * H1];
__device__ float g_mbuf[(size_t)NU * H1];
__device__ float g_sbuf[(size_t)NU * H1];
__device__ float g_ex[(size_t)E * H1];
__device__ float g_was[FM * H1];
__device__ float g_wad[FM * H1];

static inline int ceil_div(int a, int b) { return (a + b - 1) / b; }

__device__ __forceinline__ void atomicMaxF(float* addr, float v) {
    if (signbit(v)) atomicMin((unsigned int*)addr, __float_as_uint(v));
    else            atomicMax((int*)addr, __float_as_int(v));
}

// ---------------- fold W @ a  ->  wa[K,H]:  wa[k,h] = sum_c W[k,h*C+c]*a[h,c] ----
__global__ void fold_k(const float* __restrict__ W, const float* __restrict__ a,
                       float* __restrict__ wa, int K, int H, int C) {
    int t = blockIdx.x * blockDim.x + threadIdx.x;
    if (t >= K * H) return;
    int k = t / H, h = t - k * H;
    float s = 0.f;
    for (int c = 0; c < C; c++) s += W[(size_t)k * H * C + h * C + c] * a[h * C + c];
    wa[t] = s;
}

// ---------------- scores: y[n,h] = sum_k x[n,k] * wa[k,h] (warp per node) -------
template <int K, int H>
__global__ void scores_k(const float* __restrict__ x, const float* __restrict__ wa,
                         float* __restrict__ y, int n) {
    __shared__ float sw[K * H];
    int t = threadIdx.x;
    for (int i = t; i < K * H; i += blockDim.x) sw[i] = wa[i];
    __syncthreads();
    int warp = t >> 5, lane = t & 31;
    int node = blockIdx.x * (blockDim.x >> 5) + warp;
    if (node >= n) return;
    const float* row = x + (size_t)node * K;
    float acc[H] = {};
#pragma unroll
    for (int k0 = 0; k0 < K; k0 += 32) {
        float xv = row[k0 + lane];
#pragma unroll
        for (int h = 0; h < H; h++) acc[h] += xv * sw[(k0 + lane) * H + h];
    }
#pragma unroll
    for (int h = 0; h < H; h++)
#pragma unroll
        for (int o = 16; o; o >>= 1) acc[h] += __shfl_xor_sync(0xffffffffu, acc[h], o);
    if (lane == 0) {
#pragma unroll
        for (int h = 0; h < H; h++) y[(size_t)node * H + h] = acc[h];
    }
}

// ---------------- edge softmax pass 1: leaky-relu score + scatter max ----------
template <int H>
__global__ void edge_score_max_k(const int* __restrict__ src, const int* __restrict__ dst,
                                 const float* __restrict__ es, const float* __restrict__ ed,
                                 float* __restrict__ eo, float* __restrict__ m, int ne) {
    int e = blockIdx.x * blockDim.x + threadIdx.x;
    if (e >= ne) return;
    int s = src[e], d = dst[e];
#pragma unroll
    for (int h = 0; h < H; h++) {
        float v = es[(size_t)s * H + h] + ed[(size_t)d * H + h];
        v = v > 0.f ? v : 0.2f * v;
        eo[(size_t)e * H + h] = v;
        atomicMaxF(&m[(size_t)d * H + h], v);
    }
}

// ---------------- edge softmax pass 2: exp + scatter sum (float4 atomics) ------
template <int H>
__global__ void edge_expsum_k(const int* __restrict__ dst, float* __restrict__ eo,
                              const float* __restrict__ m, float* __restrict__ s, int ne) {
    int e = blockIdx.x * blockDim.x + threadIdx.x;
    if (e >= ne) return;
    int d = dst[e];
    float ex[H];
#pragma unroll
    for (int h = 0; h < H; h++) {
        ex[h] = expf(eo[(size_t)e * H + h] - m[(size_t)d * H + h]);
        eo[(size_t)e * H + h] = ex[h];
    }
#pragma unroll
    for (int hb = 0; hb < H; hb += 4) {
#if __CUDA_ARCH__ >= 900
        atomicAdd((float4*)&s[(size_t)d * H + hb],
                  make_float4(ex[hb], ex[hb + 1], ex[hb + 2], ex[hb + 3]));
#else
        for (int j = 0; j < 4; j++) atomicAdd(&s[(size_t)d * H + hb + j], ex[hb + j]);
#endif
    }
}

// ---------- pass 3a (GEMM-first): out[dst,:] += hs[src,:]*alpha[h] -------------
template <int H, int C4>
__global__ void edge_aggr_k(const int* __restrict__ src, const int* __restrict__ dst,
                            const float* __restrict__ eo, const float* __restrict__ s,
                            const float* __restrict__ hs, float* __restrict__ out, int ne) {
    constexpr int D4 = H * C4;
    int t = blockIdx.x * blockDim.x + threadIdx.x;
    if (t >= ne * D4) return;
    int e = t / D4, q = t - e * D4;
    int h = q / C4;
    int sd = dst[e];
    float alpha = eo[(size_t)e * H + h] / (s[(size_t)sd * H + h] + 1e-16f);
    float4 v = *(const float4*)&hs[(size_t)src[e] * (D4 * 4) + q * 4];
    float* o = &out[(size_t)sd * (D4 * 4) + q * 4];
#if __CUDA_ARCH__ >= 900
    atomicAdd((float4*)o, make_float4(v.x * alpha, v.y * alpha, v.z * alpha, v.w * alpha));
#else
    atomicAdd(o + 0, v.x * alpha); atomicAdd(o + 1, v.y * alpha);
    atomicAdd(o + 2, v.z * alpha); atomicAdd(o + 3, v.w * alpha);
#endif
}

// ---------- pass 3b (aggregate-first, layer2): agg[dst, h*128+j] += a_h*x[src,j]
// H2=4 heads, D1=128 src feats. Thread = (edge, j4), j4 in [0,32).
__global__ void edge_aggr_pre_k(const int* __restrict__ src, const int* __restrict__ dst,
                                const float* __restrict__ eo, const float* __restrict__ s,
                                const float* __restrict__ x, float* __restrict__ agg, int ne) {
    int t = blockIdx.x * blockDim.x + threadIdx.x;
    if (t >= ne * 32) return;
    int e = t >> 5, j = t & 31;
    int sd = dst[e];
    float4 al = *(const float4*)&eo[(size_t)e * 4];
    float4 sv = *(const float4*)&s[(size_t)sd * 4];
    float a0 = al.x / (sv.x + 1e-16f), a1 = al.y / (sv.y + 1e-16f);
    float a2 = al.z / (sv.z + 1e-16f), a3 = al.w / (sv.w + 1e-16f);
    float4 v = *(const float4*)&x[(size_t)src[e] * 128 + j * 4];
    float* base = &agg[(size_t)sd * 512 + j * 4];
#if __CUDA_ARCH__ >= 900
    atomicAdd((float4*)(base + 0),   make_float4(v.x * a0, v.y * a0, v.z * a0, v.w * a0));
    atomicAdd((float4*)(base + 128), make_float4(v.x * a1, v.y * a1, v.z * a1, v.w * a1));
    atomicAdd((float4*)(base + 256), make_float4(v.x * a2, v.y * a2, v.z * a2, v.w * a2));
    atomicAdd((float4*)(base + 384), make_float4(v.x * a3, v.y * a3, v.z * a3, v.w * a3));
#else
    for (int j2 = 0; j2 < 4; j2++) {
        float vv = (&v.x)[j2];
        atomicAdd(base + 0   + j2, vv * a0); atomicAdd(base + 128 + j2, vv * a1);
        atomicAdd(base + 256 + j2, vv * a2); atomicAdd(base + 384 + j2, vv * a3);
    }
#endif
}

// ------------- fp32 SIMT GEMM with strides + optional bias/relu ----------------
// C[M, 128-tile] = A[M,K](lda) @ B[K,N](ldb); 128x128 tile, 8x8 micro.
__global__ void sgemm_k(const float* __restrict__ A, int lda,
                        const float* __restrict__ B, int ldb,
                        float* __restrict__ C, int ldc,
                        int M, int K, const float* __restrict__ bias, int relu) {
    __shared__ float As[8][128];
    __shared__ float Bs[8][128];
    int t  = threadIdx.x;
    int tx = t & 15, ty = t >> 4;
    int row0 = blockIdx.y * 128, col0 = blockIdx.x * 128;
    float acc[8][8] = {};
    for (int k0 = 0; k0 < K; k0 += 8) {
        {
            int m = t >> 1, k4 = (t & 1) * 4;
            int r = row0 + m;
            float4 v = make_float4(0.f, 0.f, 0.f, 0.f);
            if (r < M) v = *(const float4*)&A[(size_t)r * lda + k0 + k4];
            As[k4 + 0][m] = v.x; As[k4 + 1][m] = v.y;
            As[k4 + 2][m] = v.z; As[k4 + 3][m] = v.w;
        }
        {
            int kk = t >> 5, n4 = (t & 31) * 4;
            *(float4*)&Bs[kk][n4] = *(const float4*)&B[(size_t)(k0 + kk) * ldb + col0 + n4];
        }
        __syncthreads();
#pragma unroll
        for (int kk = 0; kk < 8; kk++) {
            float a_[8], b_[8];
            *(float4*)&a_[0] = *(const float4*)&As[kk][ty * 8];
            *(float4*)&a_[4] = *(const float4*)&As[kk][ty * 8 + 4];
            *(float4*)&b_[0] = *(const float4*)&Bs[kk][tx * 8];
            *(float4*)&b_[4] = *(const float4*)&Bs[kk][tx * 8 + 4];
#pragma unroll
            for (int i = 0; i < 8; i++)
#pragma unroll
                for (int j = 0; j < 8; j++) acc[i][j] += a_[i] * b_[j];
        }
        __syncthreads();
    }
    float bv[8];
#pragma unroll
    for (int j = 0; j < 8; j++) bv[j] = bias ? bias[col0 + tx * 8 + j] : 0.f;
    for (int i = 0; i < 8; i++) {
        int r = row0 + ty * 8 + i;
        if (r >= M) break;
#pragma unroll
        for (int j4 = 0; j4 < 8; j4 += 4) {
            float4 v = make_float4(acc[i][j4] + bv[j4], acc[i][j4 + 1] + bv[j4 + 1],
                                   acc[i][j4 + 2] + bv[j4 + 2], acc[i][j4 + 3] + bv[j4 + 3]);
            if (relu) {
                v.x = fmaxf(v.x, 0.f); v.y = fmaxf(v.y, 0.f);
                v.z = fmaxf(v.z, 0.f); v.w = fmaxf(v.w, 0.f);
            }
            *(float4*)&C[(size_t)r * ldc + col0 + tx * 8 + j4] = v;
        }
    }
}

// ---------------- bias (+ optional relu), in place -----------------------------
__global__ void bias_act_k(float* __restrict__ z, const float* __restrict__ b,
                           int n, int D, int relu) {
    int D4 = D >> 2;
    int t = blockIdx.x * blockDim.x + threadIdx.x;
    if (t >= n * D4) return;
    int q = t % D4;
    float4 v = *(float4*)&z[(size_t)t * 4];
    float4 bb = *(const float4*)&b[q * 4];
    v.x += bb.x; v.y += bb.y; v.z += bb.z; v.w += bb.w;
    if (relu) {
        v.x = fmaxf(v.x, 0.f); v.y = fmaxf(v.y, 0.f);
        v.z = fmaxf(v.z, 0.f); v.w = fmaxf(v.w, 0.f);
    }
    *(float4*)&z[(size_t)t * 4] = v;
}

// ---------------- edge decoder (gathered-A GEMM + fused MLP epilogue) ----------
__global__ void dec_gemm_k(const float* __restrict__ zu2, const float* __restrict__ zm2,
                           const int* __restrict__ lu, const int* __restrict__ lm,
                           const float* __restrict__ dw1, const float* __restrict__ db1,
                           const float* __restrict__ dw2, const float* __restrict__ db2,
                           float* __restrict__ out, int M) {
    __shared__ float As[32][129];
    __shared__ float Bs[32][16];
    int t  = threadIdx.x;
    int tx = t & 15, ty = t >> 4;
    int row0 = blockIdx.x * 128;
    float acc[8] = {};
    for (int k0 = 0; k0 < 2 * D2; k0 += 32) {
#pragma unroll
        for (int l = 0; l < 4; l++) {
            int i = t + l * 256;
            int row = i >> 3, k4 = (i & 7) * 4;
            int r = row0 + row;
            float4 v = make_float4(0.f, 0.f, 0.f, 0.f);
            if (r < M) {
                int kk = k0 + k4;
                const float* base = (kk < D2) ? (zu2 + (size_t)lu[r] * D2 + kk)
                                              : (zm2 + (size_t)lm[r] * D2 + (kk - D2));
                v = *(const float4*)base;
            }
            As[k4 + 0][row] = v.x; As[k4 + 1][row] = v.y;
            As[k4 + 2][row] = v.z; As[k4 + 3][row] = v.w;
        }
        if (t < 128) {
            int kk = t >> 2, j4 = (t & 3) * 4;
            *(float4*)&Bs[kk][j4] = *(const float4*)&dw1[(size_t)(k0 + kk) * HID + j4];
        }
        __syncthreads();
#pragma unroll
        for (int kk = 0; kk < 32; kk++) {
            float b = Bs[kk][tx];
            const float* arow = &As[kk][ty * 8];
#pragma unroll
            for (int i = 0; i < 8; i++) acc[i] += arow[i] * b;
        }
        __syncthreads();
    }
    float db1v = db1[tx];
    float dw2v = dw2[tx];
    float b2   = db2[0];
#pragma unroll
    for (int i = 0; i < 8; i++) {
        float h = fmaxf(acc[i] + db1v, 0.f);
        float term = h * dw2v;
        term += __shfl_xor_sync(0xffffffffu, term, 1);
        term += __shfl_xor_sync(0xffffffffu, term, 2);
        term += __shfl_xor_sync(0xffffffffu, term, 4);
        term += __shfl_xor_sync(0xffffffffu, term, 8);
        if (tx == 0) {
            int r = row0 + ty * 8 + i;
            if (r < M) out[r] = term + b2;
        }
    }
}

// ---------------- launch --------------------------------------------------------
extern "C" void kernel_launch(void* const* d_in, const int* in_sizes, int n_in,
                              void* d_out, int out_size) {
    const float* xu     = (const float*)d_in[0];
    const float* xm     = (const float*)d_in[1];
    const int*   um_src = (const int*)d_in[2];
    const int*   um_dst = (const int*)d_in[3];
    const int*   mu_src = (const int*)d_in[4];
    const int*   mu_dst = (const int*)d_in[5];
    const int*   lab_u  = (const int*)d_in[6];
    const int*   lab_m  = (const int*)d_in[7];
    const float* w1um_s = (const float*)d_in[8];
    const float* w1um_d = (const float*)d_in[9];
    const float* a1um_s = (const float*)d_in[10];
    const float* a1um_d = (const float*)d_in[11];
    const float* b1um   = (const float*)d_in[12];
    const float* w1mu_s = (const float*)d_in[13];
    const float* w1mu_d = (const float*)d_in[14];
    const float* a1mu_s = (const float*)d_in[15];
    const float* a1mu_d = (const float*)d_in[16];
    const float* b1mu   = (const float*)d_in[17];
    const float* w2um_s = (const float*)d_in[18];
    const float* w2um_d = (const float*)d_in[19];
    const float* a2um_s = (const float*)d_in[20];
    const float* a2um_d = (const float*)d_in[21];
    const float* b2um   = (const float*)d_in[22];
    const float* w2mu_s = (const float*)d_in[23];
    const float* w2mu_d = (const float*)d_in[24];
    const float* a2mu_s = (const float*)d_in[25];
    const float* a2mu_d = (const float*)d_in[26];
    const float* b2mu   = (const float*)d_in[27];
    const float* dw1    = (const float*)d_in[28];
    const float* db1    = (const float*)d_in[29];
    const float* dw2    = (const float*)d_in[30];
    const float* db2    = (const float*)d_in[31];
    float* out = (float*)d_out;

    float *hs1um, *hs1mu, *hs2mu, *agg, *zu, *zm, *zu2, *zm2, *es, *ed, *mm, *ss, *ex, *was, *wad;
    cudaGetSymbolAddress((void**)&hs1um, g_hs1um);
    cudaGetSymbolAddress((void**)&hs1mu, g_hs1mu);
    cudaGetSymbolAddress((void**)&hs2mu, g_hs2mu);
    cudaGetSymbolAddress((void**)&agg,   g_agg);
    cudaGetSymbolAddress((void**)&zu,  g_zu);
    cudaGetSymbolAddress((void**)&zm,  g_zm);
    cudaGetSymbolAddress((void**)&zu2, g_zu2);
    cudaGetSymbolAddress((void**)&zm2, g_zm2);
    cudaGetSymbolAddress((void**)&es,  g_es);
    cudaGetSymbolAddress((void**)&ed,  g_ed);
    cudaGetSymbolAddress((void**)&mm,  g_mbuf);
    cudaGetSymbolAddress((void**)&ss,  g_sbuf);
    cudaGetSymbolAddress((void**)&ex,  g_ex);
    cudaGetSymbolAddress((void**)&was, g_was);
    cudaGetSymbolAddress((void**)&wad, g_wad);

    const int TB = 256;

    // ================= layer 1, user -> movie (GEMM-first) =================
    fold_k<<<ceil_div(FU * H1, TB), TB>>>(w1um_s, a1um_s, was, FU, H1, C1);
    fold_k<<<ceil_div(FM * H1, TB), TB>>>(w1um_d, a1um_d, wad, FM, H1, C1);
    scores_k<FU, H1><<<ceil_div(NU, 8), 256>>>(xu, was, es, NU);
    scores_k<FM, H1><<<ceil_div(NM, 8), 256>>>(xm, wad, ed, NM);
    sgemm_k<<<dim3(1, ceil_div(NU, 128)), 256>>>(xu, FU, w1um_s, D1, hs1um, D1, NU, FU, nullptr, 0);
    cudaMemsetAsync(mm, 0xFF, (size_t)NM * H1 * sizeof(float));
    cudaMemsetAsync(ss, 0, (size_t)NM * H1 * sizeof(float));
    cudaMemsetAsync(zm, 0, (size_t)NM * D1 * sizeof(float));
    edge_score_max_k<H1><<<ceil_div(E, TB), TB>>>(um_src, um_dst, es, ed, ex, mm, E);
    edge_expsum_k<H1><<<ceil_div(E, TB), TB>>>(um_dst, ex, mm, ss, E);
    edge_aggr_k<H1, C1 / 4><<<ceil_div(E * (D1 / 4), TB), TB>>>(um_src, um_dst, ex, ss, hs1um, zm, E);
    bias_act_k<<<ceil_div(NM * D1 / 4, TB), TB>>>(zm, b1um, NM, D1, 1);

    // ================= layer 1, movie -> user (GEMM-first) =================
    fold_k<<<ceil_div(FM * H1, TB), TB>>>(w1mu_s, a1mu_s, was, FM, H1, C1);
    fold_k<<<ceil_div(FU * H1, TB), TB>>>(w1mu_d, a1mu_d, wad, FU, H1, C1);
    scores_k<FM, H1><<<ceil_div(NM, 8), 256>>>(xm, was, es, NM);
    scores_k<FU, H1><<<ceil_div(NU, 8), 256>>>(xu, wad, ed, NU);
    sgemm_k<<<dim3(1, ceil_div(NM, 128)), 256>>>(xm, FM, w1mu_s, D1, hs1mu, D1, NM, FM, nullptr, 0);
    cudaMemsetAsync(mm, 0xFF, (size_t)NU * H1 * sizeof(float));
    cudaMemsetAsync(ss, 0, (size_t)NU * H1 * sizeof(float));
    cudaMemsetAsync(zu, 0, (size_t)NU * D1 * sizeof(float));
    edge_score_max_k<H1><<<ceil_div(E, TB), TB>>>(mu_src, mu_dst, es, ed, ex, mm, E);
    edge_expsum_k<H1><<<ceil_div(E, TB), TB>>>(mu_dst, ex, mm, ss, E);
    edge_aggr_k<H1, C1 / 4><<<ceil_div(E * (D1 / 4), TB), TB>>>(mu_src, mu_dst, ex, ss, hs1mu, zu, E);
    bias_act_k<<<ceil_div(NU * D1 / 4, TB), TB>>>(zu, b1mu, NU, D1, 1);

    // ========= layer 2, user -> movie (AGGREGATE-FIRST: agg zu, then GEMM) =========
    fold_k<<<ceil_div(D1 * H2, TB), TB>>>(w2um_s, a2um_s, was, D1, H2, C2);
    fold_k<<<ceil_div(D1 * H2, TB), TB>>>(w2um_d, a2um_d, wad, D1, H2, C2);
    scores_k<D1, H2><<<ceil_div(NU, 8), 256>>>(zu, was, es, NU);
    scores_k<D1, H2><<<ceil_div(NM, 8), 256>>>(zm, wad, ed, NM);
    cudaMemsetAsync(mm, 0xFF, (size_t)NM * H2 * sizeof(float));
    cudaMemsetAsync(ss, 0, (size_t)NM * H2 * sizeof(float));
    cudaMemsetAsync(agg, 0, (size_t)NM * D2 * sizeof(float));
    edge_score_max_k<H2><<<ceil_div(E, TB), TB>>>(um_src, um_dst, es, ed, ex, mm, E);
    edge_expsum_k<H2><<<ceil_div(E, TB), TB>>>(um_dst, ex, mm, ss, E);
    edge_aggr_pre_k<<<ceil_div(E * 32, TB), TB>>>(um_src, um_dst, ex, ss, zu, agg, E);
    for (int h = 0; h < H2; h++) {  // zm2[:, h*128:+128] = agg_h @ W_h + b
        sgemm_k<<<dim3(1, ceil_div(NM, 128)), 256>>>(agg + h * 128, D2, w2um_s + h * 128, D2,
                                                     zm2 + h * 128, D2, NM, D1, b2um + h * 128, 0);
    }

    // ========= layer 2, movie -> user (GEMM-first on movies) =========
    fold_k<<<ceil_div(D1 * H2, TB), TB>>>(w2mu_s, a2mu_s, was, D1, H2, C2);
    fold_k<<<ceil_div(D1 * H2, TB), TB>>>(w2mu_d, a2mu_d, wad, D1, H2, C2);
    scores_k<D1, H2><<<ceil_div(NM, 8), 256>>>(zm, was, es, NM);
    scores_k<D1, H2><<<ceil_div(NU, 8), 256>>>(zu, wad, ed, NU);
    sgemm_k<<<dim3(D2 / 128, ceil_div(NM, 128)), 256>>>(zm, D1, w2mu_s, D2, hs2mu, D2, NM, D1, nullptr, 0);
    cudaMemsetAsync(mm, 0xFF, (size_t)NU * H2 * sizeof(float));
    cudaMemsetAsync(ss, 0, (size_t)NU * H2 * sizeof(float));
    cudaMemsetAsync(zu2, 0, (size_t)NU * D2 * sizeof(float));
    edge_score_max_k<H2><<<ceil_div(E, TB), TB>>>(mu_src, mu_dst, es, ed, ex, mm, E);
    edge_expsum_k<H2><<<ceil_div(E, TB), TB>>>(mu_dst, ex, mm, ss, E);
    edge_aggr_k<H2, C2 / 4><<<ceil_div(E * (D2 / 4), TB), TB>>>(mu_src, mu_dst, ex, ss, hs2mu, zu2, E);
    bias_act_k<<<ceil_div(NU * D2 / 4, TB), TB>>>(zu2, b2mu, NU, D2, 0);

    // ================= decoder =================
    dec_gemm_k<<<ceil_div(EL, 128), 256>>>(zu2, zm2, lab_u, lab_m, dw1, db1, dw2, db2, out, EL);
}

// round 4
// speedup vs baseline: 1.8258x; 1.3256x over previous
#include <cuda_runtime.h>
#include <math.h>

// ---------------- problem constants ----------------
constexpr int NU = 100000, NM = 20000;
constexpr int FU = 32, FM = 128;
constexpr int H1 = 8, C1 = 16, D1 = 128;   // layer 1
constexpr int H2 = 4, C2 = 128, D2 = 512;  // layer 2
constexpr int E = 250000, EL = 200000;
constexpr int HID = 16;

// ---------------- device scratch (static; no allocs allowed) ----------------
__device__ float g_hs1um[(size_t)NU * D1];
__device__ float g_hs1mu[(size_t)NM * D1];
__device__ float g_hs2mu[(size_t)NM * D2];
__device__ float g_agg[(size_t)NM * D2];
__device__ float g_zu[(size_t)NU * D1];
__device__ float g_zm[(size_t)NM * D1];
__device__ float g_zu2[(size_t)NU * D2];
__device__ float g_zm2[(size_t)NM * D2];
__device__ float g_su1[(size_t)NU * H1];   // scores from user-side features
__device__ float g_su2[(size_t)NU * H1];
__device__ float g_sm1[(size_t)NM * H1];   // scores from movie-side features
__device__ float g_sm2[(size_t)NM * H1];
__device__ float g_wa1[FM * H1];
__device__ float g_wa2[FM * H1];
__device__ float g_wa3[FM * H1];
__device__ float g_wa4[FM * H1];
// CSR
__device__ int g_rp_um[NM + 1];
__device__ int g_rp_mu[NU + 1];
__device__ int g_csr_um[E];
__device__ int g_csr_mu[E];
__device__ int g_cnt_um[NM];
__device__ int g_cnt_mu[NU];
__device__ int g_bsum[256];

static inline int ceil_div(int a, int b) { return (a + b - 1) / b; }

// ================= CSR build =================
__global__ void hist2_k(const int* __restrict__ d1, const int* __restrict__ d2,
                        int* __restrict__ c1, int* __restrict__ c2, int ne) {
    int e = blockIdx.x * blockDim.x + threadIdx.x;
    if (e >= ne) return;
    atomicAdd(&c1[d1[e]], 1);
    atomicAdd(&c2[d2[e]], 1);
}

// block handles 1024 elems -> bsum[b]
__global__ void blk_reduce_k(const int* __restrict__ deg, int* __restrict__ bsum, int n) {
    __shared__ int sh[256];
    int b = blockIdx.x, tid = threadIdx.x;
    int base = b * 1024;
    int s = 0;
    for (int i = tid; i < 1024; i += 256) {
        int idx = base + i;
        if (idx < n) s += deg[idx];
    }
    sh[tid] = s; __syncthreads();
    for (int o = 128; o; o >>= 1) { if (tid < o) sh[tid] += sh[tid + o]; __syncthreads(); }
    if (tid == 0) bsum[b] = sh[0];
}

__global__ void scan_bsum_k(int* __restrict__ bsum, int nb) {
    if (threadIdx.x == 0) {
        int acc = 0;
        for (int i = 0; i < nb; i++) { int v = bsum[i]; bsum[i] = acc; acc += v; }
    }
}

__global__ void blk_scan_k(const int* __restrict__ deg, const int* __restrict__ bsum,
                           int* __restrict__ rowptr, int n, int ne) {
    __shared__ int ts[256];
    int b = blockIdx.x, tid = threadIdx.x;
    int base = b * 1024 + tid * 4;
    int v[4]; int loc = 0;
#pragma unroll
    for (int j = 0; j < 4; j++) { int idx = base + j; v[j] = (idx < n) ? deg[idx] : 0; loc += v[j]; }
    ts[tid] = loc; __syncthreads();
    // inclusive Hillis-Steele
    for (int o = 1; o < 256; o <<= 1) {
        int t = (tid >= o) ? ts[tid - o] : 0;
        __syncthreads();
        ts[tid] += t;
        __syncthreads();
    }
    int excl = ts[tid] - loc + bsum[b];
#pragma unroll
    for (int j = 0; j < 4; j++) {
        int idx = base + j;
        if (idx < n) rowptr[idx] = excl;
        excl += v[j];
    }
    if (b == 0 && tid == 0) rowptr[n] = ne;
}

__global__ void scatter2_k(const int* __restrict__ s1, const int* __restrict__ d1,
                           const int* __restrict__ rp1, int* __restrict__ c1, int* __restrict__ o1,
                           const int* __restrict__ s2, const int* __restrict__ d2,
                           const int* __restrict__ rp2, int* __restrict__ c2, int* __restrict__ o2,
                           int ne) {
    int e = blockIdx.x * blockDim.x + threadIdx.x;
    if (e >= ne) return;
    { int d = d1[e]; int p = rp1[d] + atomicAdd(&c1[d], 1); o1[p] = s1[e]; }
    { int d = d2[e]; int p = rp2[d] + atomicAdd(&c2[d], 1); o2[p] = s2[e]; }
}

// ================= fold W @ a -> wa[K,H] =================
__global__ void fold_k(const float* __restrict__ W, const float* __restrict__ a,
                       float* __restrict__ wa, int K, int H, int C) {
    int t = blockIdx.x * blockDim.x + threadIdx.x;
    if (t >= K * H) return;
    int k = t / H, h = t - k * H;
    float s = 0.f;
    for (int c = 0; c < C; c++) s += W[(size_t)k * H * C + h * C + c] * a[h * C + c];
    wa[t] = s;
}

// ====== scores: read x once, produce y1 = x@wa1, y2 = x@wa2 (warp per node) =====
template <int K, int H>
__global__ void scores2_k(const float* __restrict__ x,
                          const float* __restrict__ wa1, const float* __restrict__ wa2,
                          float* __restrict__ y1, float* __restrict__ y2, int n) {
    __shared__ float s1[K * H], s2[K * H];
    int t = threadIdx.x;
    for (int i = t; i < K * H; i += blockDim.x) { s1[i] = wa1[i]; s2[i] = wa2[i]; }
    __syncthreads();
    int warp = t >> 5, lane = t & 31;
    int node = blockIdx.x * (blockDim.x >> 5) + warp;
    if (node >= n) return;
    const float* row = x + (size_t)node * K;
    float a1[H] = {}, a2[H] = {};
#pragma unroll
    for (int k0 = 0; k0 < K; k0 += 32) {
        float xv = row[k0 + lane];
#pragma unroll
        for (int h = 0; h < H; h++) {
            a1[h] += xv * s1[(k0 + lane) * H + h];
            a2[h] += xv * s2[(k0 + lane) * H + h];
        }
    }
#pragma unroll
    for (int h = 0; h < H; h++) {
#pragma unroll
        for (int o = 16; o; o >>= 1) {
            a1[h] += __shfl_xor_sync(0xffffffffu, a1[h], o);
            a2[h] += __shfl_xor_sync(0xffffffffu, a2[h], o);
        }
    }
    if (lane == 0) {
#pragma unroll
        for (int h = 0; h < H; h++) {
            y1[(size_t)node * H + h] = a1[h];
            y2[(size_t)node * H + h] = a2[h];
        }
    }
}

// ====== fused GAT aggregation (GEMM-first): warp per dst, no atomics ======
// out[d, :] = bias + sum_e alpha_{e,h} * feat[src_e, :], optional relu.
template <int H, int C>
__global__ void gat_aggr_k(const int* __restrict__ rowptr, const int* __restrict__ csr,
                           const float* __restrict__ es, const float* __restrict__ ed,
                           const float* __restrict__ feat, const float* __restrict__ bias,
                           float* __restrict__ out, int nd, int relu) {
    constexpr int D = H * C;
    constexpr int NV = D / 128;
    int w = (blockIdx.x * blockDim.x + threadIdx.x) >> 5;
    int lane = threadIdx.x & 31;
    if (w >= nd) return;
    int rs = rowptr[w], re = rowptr[w + 1];
    float edv[H], m[H], ssum[H];
#pragma unroll
    for (int h = 0; h < H; h++) { edv[h] = ed[(size_t)w * H + h]; m[h] = -INFINITY; ssum[h] = 0.f; }
    for (int i = rs + lane; i < re; i += 32) {
        int s = csr[i];
#pragma unroll
        for (int h = 0; h < H; h++) {
            float e = es[(size_t)s * H + h] + edv[h];
            e = e > 0.f ? e : 0.2f * e;
            m[h] = fmaxf(m[h], e);
        }
    }
#pragma unroll
    for (int h = 0; h < H; h++)
#pragma unroll
        for (int o = 16; o; o >>= 1) m[h] = fmaxf(m[h], __shfl_xor_sync(0xffffffffu, m[h], o));
    for (int i = rs + lane; i < re; i += 32) {
        int s = csr[i];
#pragma unroll
        for (int h = 0; h < H; h++) {
            float e = es[(size_t)s * H + h] + edv[h];
            e = e > 0.f ? e : 0.2f * e;
            ssum[h] += __expf(e - m[h]);
        }
    }
#pragma unroll
    for (int h = 0; h < H; h++) {
#pragma unroll
        for (int o = 16; o; o >>= 1) ssum[h] += __shfl_xor_sync(0xffffffffu, ssum[h], o);
        ssum[h] = 1.f / (ssum[h] + 1e-16f);
    }
    float4 acc[NV];
#pragma unroll
    for (int v = 0; v < NV; v++) acc[v] = make_float4(0.f, 0.f, 0.f, 0.f);
#pragma unroll 2
    for (int i = rs; i < re; i++) {
        int s = csr[i];
#pragma unroll
        for (int v = 0; v < NV; v++) {
            int h = (v * 128 + lane * 4) / C;
            float e = es[(size_t)s * H + h] + edv[h];
            e = e > 0.f ? e : 0.2f * e;
            float a = __expf(e - m[h]) * ssum[h];
            float4 x = *(const float4*)&feat[(size_t)s * D + v * 128 + lane * 4];
            acc[v].x += a * x.x; acc[v].y += a * x.y;
            acc[v].z += a * x.z; acc[v].w += a * x.w;
        }
    }
#pragma unroll
    for (int v = 0; v < NV; v++) {
        float4 bb = *(const float4*)&bias[v * 128 + lane * 4];
        float4 o = make_float4(acc[v].x + bb.x, acc[v].y + bb.y, acc[v].z + bb.z, acc[v].w + bb.w);
        if (relu) {
            o.x = fmaxf(o.x, 0.f); o.y = fmaxf(o.y, 0.f);
            o.z = fmaxf(o.z, 0.f); o.w = fmaxf(o.w, 0.f);
        }
        *(float4*)&out[(size_t)w * D + v * 128 + lane * 4] = o;
    }
}

// ====== fused aggregate-first (layer2 um): agg[d, h*128+j] = sum alpha_h x[src,j] ===
__global__ void gat_aggr_pre4_k(const int* __restrict__ rowptr, const int* __restrict__ csr,
                                const float* __restrict__ es, const float* __restrict__ ed,
                                const float* __restrict__ x, float* __restrict__ agg, int nd) {
    int w = (blockIdx.x * blockDim.x + threadIdx.x) >> 5;
    int lane = threadIdx.x & 31;
    if (w >= nd) return;
    int rs = rowptr[w], re = rowptr[w + 1];
    float edv[4], m[4], ssum[4];
#pragma unroll
    for (int h = 0; h < 4; h++) { edv[h] = ed[(size_t)w * 4 + h]; m[h] = -INFINITY; ssum[h] = 0.f; }
    for (int i = rs + lane; i < re; i += 32) {
        int s = csr[i];
        float4 ev = *(const float4*)&es[(size_t)s * 4];
        float e4[4] = { ev.x, ev.y, ev.z, ev.w };
#pragma unroll
        for (int h = 0; h < 4; h++) {
            float e = e4[h] + edv[h];
            e = e > 0.f ? e : 0.2f * e;
            m[h] = fmaxf(m[h], e);
        }
    }
#pragma unroll
    for (int h = 0; h < 4; h++)
#pragma unroll
        for (int o = 16; o; o >>= 1) m[h] = fmaxf(m[h], __shfl_xor_sync(0xffffffffu, m[h], o));
    for (int i = rs + lane; i < re; i += 32) {
        int s = csr[i];
        float4 ev = *(const float4*)&es[(size_t)s * 4];
        float e4[4] = { ev.x, ev.y, ev.z, ev.w };
#pragma unroll
        for (int h = 0; h < 4; h++) {
            float e = e4[h] + edv[h];
            e = e > 0.f ? e : 0.2f * e;
            ssum[h] += __expf(e - m[h]);
        }
    }
#pragma unroll
    for (int h = 0; h < 4; h++) {
#pragma unroll
        for (int o = 16; o; o >>= 1) ssum[h] += __shfl_xor_sync(0xffffffffu, ssum[h], o);
        ssum[h] = 1.f / (ssum[h] + 1e-16f);
    }
    float4 acc[4];
#pragma unroll
    for (int h = 0; h < 4; h++) acc[h] = make_float4(0.f, 0.f, 0.f, 0.f);
#pragma unroll 2
    for (int i = rs; i < re; i++) {
        int s = csr[i];
        float4 ev = *(const float4*)&es[(size_t)s * 4];
        float e4[4] = { ev.x, ev.y, ev.z, ev.w };
        float4 xv = *(const float4*)&x[(size_t)s * 128 + lane * 4];
#pragma unroll
        for (int h = 0; h < 4; h++) {
            float e = e4[h] + edv[h];
            e = e > 0.f ? e : 0.2f * e;
            float a = __expf(e - m[h]) * ssum[h];
            acc[h].x += a * xv.x; acc[h].y += a * xv.y;
            acc[h].z += a * xv.z; acc[h].w += a * xv.w;
        }
    }
#pragma unroll
    for (int h = 0; h < 4; h++)
        *(float4*)&agg[(size_t)w * 512 + h * 128 + lane * 4] = acc[h];
}

// ------------- fp32 SIMT GEMM (128x128 tile, 8x8 micro), optional block-diag ---
// If diag: C[:,col0:+128] = A[:,col0+k](lda) @ B[k, col0:+128](ldb), k in [0,K)
// (kof shifts ONLY the A column window; B rows always start at 0.)
__global__ void sgemm_k(const float* __restrict__ A, int lda,
                        const float* __restrict__ B, int ldb,
                        float* __restrict__ C, int ldc,
                        int M, int K, const float* __restrict__ bias, int relu, int diag) {
    __shared__ float As[8][128];
    __shared__ float Bs[8][128];
    int t  = threadIdx.x;
    int tx = t & 15, ty = t >> 4;
    int row0 = blockIdx.y * 128, col0 = blockIdx.x * 128;
    int kof = diag ? col0 : 0;
    float acc[8][8] = {};
    for (int k0 = 0; k0 < K; k0 += 8) {
        {
            int m = t >> 1, k4 = (t & 1) * 4;
            int r = row0 + m;
            float4 v = make_float4(0.f, 0.f, 0.f, 0.f);
            if (r < M) v = *(const float4*)&A[(size_t)r * lda + kof + k0 + k4];
            As[k4 + 0][m] = v.x; As[k4 + 1][m] = v.y;
            As[k4 + 2][m] = v.z; As[k4 + 3][m] = v.w;
        }
        {
            int kk = t >> 5, n4 = (t & 31) * 4;
            *(float4*)&Bs[kk][n4] = *(const float4*)&B[(size_t)(k0 + kk) * ldb + col0 + n4];
        }
        __syncthreads();
#pragma unroll
        for (int kk = 0; kk < 8; kk++) {
            float a_[8], b_[8];
            *(float4*)&a_[0] = *(const float4*)&As[kk][ty * 8];
            *(float4*)&a_[4] = *(const float4*)&As[kk][ty * 8 + 4];
            *(float4*)&b_[0] = *(const float4*)&Bs[kk][tx * 8];
            *(float4*)&b_[4] = *(const float4*)&Bs[kk][tx * 8 + 4];
#pragma unroll
            for (int i = 0; i < 8; i++)
#pragma unroll
                for (int j = 0; j < 8; j++) acc[i][j] += a_[i] * b_[j];
        }
        __syncthreads();
    }
    float bv[8];
#pragma unroll
    for (int j = 0; j < 8; j++) bv[j] = bias ? bias[col0 + tx * 8 + j] : 0.f;
    for (int i = 0; i < 8; i++) {
        int r = row0 + ty * 8 + i;
        if (r >= M) break;
#pragma unroll
        for (int j4 = 0; j4 < 8; j4 += 4) {
            float4 v = make_float4(acc[i][j4] + bv[j4], acc[i][j4 + 1] + bv[j4 + 1],
                                   acc[i][j4 + 2] + bv[j4 + 2], acc[i][j4 + 3] + bv[j4 + 3]);
            if (relu) {
                v.x = fmaxf(v.x, 0.f); v.y = fmaxf(v.y, 0.f);
                v.z = fmaxf(v.z, 0.f); v.w = fmaxf(v.w, 0.f);
            }
            *(float4*)&C[(size_t)r * ldc + col0 + tx * 8 + j4] = v;
        }
    }
}

// ---------------- edge decoder (gathered-A GEMM + fused MLP epilogue) ----------
__global__ void dec_gemm_k(const float* __restrict__ zu2, const float* __restrict__ zm2,
                           const int* __restrict__ lu, const int* __restrict__ lm,
                           const float* __restrict__ dw1, const float* __restrict__ db1,
                           const float* __restrict__ dw2, const float* __restrict__ db2,
                           float* __restrict__ out, int M) {
    __shared__ float As[32][129];
    __shared__ float Bs[32][16];
    int t  = threadIdx.x;
    int tx = t & 15, ty = t >> 4;
    int row0 = blockIdx.x * 128;
    float acc[8] = {};
    for (int k0 = 0; k0 < 2 * D2; k0 += 32) {
#pragma unroll
        for (int l = 0; l < 4; l++) {
            int i = t + l * 256;
            int row = i >> 3, k4 = (i & 7) * 4;
            int r = row0 + row;
            float4 v = make_float4(0.f, 0.f, 0.f, 0.f);
            if (r < M) {
                int kk = k0 + k4;
                const float* base = (kk < D2) ? (zu2 + (size_t)lu[r] * D2 + kk)
                                              : (zm2 + (size_t)lm[r] * D2 + (kk - D2));
                v = *(const float4*)base;
            }
            As[k4 + 0][row] = v.x; As[k4 + 1][row] = v.y;
            As[k4 + 2][row] = v.z; As[k4 + 3][row] = v.w;
        }
        if (t < 128) {
            int kk = t >> 2, j4 = (t & 3) * 4;
            *(float4*)&Bs[kk][j4] = *(const float4*)&dw1[(size_t)(k0 + kk) * HID + j4];
        }
        __syncthreads();
#pragma unroll
        for (int kk = 0; kk < 32; kk++) {
            float b = Bs[kk][tx];
            const float* arow = &As[kk][ty * 8];
#pragma unroll
            for (int i = 0; i < 8; i++) acc[i] += arow[i] * b;
        }
        __syncthreads();
    }
    float db1v = db1[tx];
    float dw2v = dw2[tx];
    float b2   = db2[0];
#pragma unroll
    for (int i = 0; i < 8; i++) {
        float h = fmaxf(acc[i] + db1v, 0.f);
        float term = h * dw2v;
        term += __shfl_xor_sync(0xffffffffu, term, 1);
        term += __shfl_xor_sync(0xffffffffu, term, 2);
        term += __shfl_xor_sync(0xffffffffu, term, 4);
        term += __shfl_xor_sync(0xffffffffu, term, 8);
        if (tx == 0) {
            int r = row0 + ty * 8 + i;
            if (r < M) out[r] = term + b2;
        }
    }
}

// ---------------- launch --------------------------------------------------------
extern "C" void kernel_launch(void* const* d_in, const int* in_sizes, int n_in,
                              void* d_out, int out_size) {
    const float* xu     = (const float*)d_in[0];
    const float* xm     = (const float*)d_in[1];
    const int*   um_src = (const int*)d_in[2];
    const int*   um_dst = (const int*)d_in[3];
    const int*   mu_src = (const int*)d_in[4];
    const int*   mu_dst = (const int*)d_in[5];
    const int*   lab_u  = (const int*)d_in[6];
    const int*   lab_m  = (const int*)d_in[7];
    const float* w1um_s = (const float*)d_in[8];
    const float* w1um_d = (const float*)d_in[9];
    const float* a1um_s = (const float*)d_in[10];
    const float* a1um_d = (const float*)d_in[11];
    const float* b1um   = (const float*)d_in[12];
    const float* w1mu_s = (const float*)d_in[13];
    const float* w1mu_d = (const float*)d_in[14];
    const float* a1mu_s = (const float*)d_in[15];
    const float* a1mu_d = (const float*)d_in[16];
    const float* b1mu   = (const float*)d_in[17];
    const float* w2um_s = (const float*)d_in[18];
    const float* w2um_d = (const float*)d_in[19];
    const float* a2um_s = (const float*)d_in[20];
    const float* a2um_d = (const float*)d_in[21];
    const float* b2um   = (const float*)d_in[22];
    const float* w2mu_s = (const float*)d_in[23];
    const float* w2mu_d = (const float*)d_in[24];
    const float* a2mu_s = (const float*)d_in[25];
    const float* a2mu_d = (const float*)d_in[26];
    const float* b2mu   = (const float*)d_in[27];
    const float* dw1    = (const float*)d_in[28];
    const float* db1    = (const float*)d_in[29];
    const float* dw2    = (const float*)d_in[30];
    const float* db2    = (const float*)d_in[31];
    float* out = (float*)d_out;

    float *hs1um, *hs1mu, *hs2mu, *agg, *zu, *zm, *zu2, *zm2;
    float *su1, *su2, *sm1, *sm2, *wa1, *wa2, *wa3, *wa4;
    int *rp_um, *rp_mu, *csr_um, *csr_mu, *cnt_um, *cnt_mu, *bsum;
    cudaGetSymbolAddress((void**)&hs1um, g_hs1um);
    cudaGetSymbolAddress((void**)&hs1mu, g_hs1mu);
    cudaGetSymbolAddress((void**)&hs2mu, g_hs2mu);
    cudaGetSymbolAddress((void**)&agg,   g_agg);
    cudaGetSymbolAddress((void**)&zu,  g_zu);
    cudaGetSymbolAddress((void**)&zm,  g_zm);
    cudaGetSymbolAddress((void**)&zu2, g_zu2);
    cudaGetSymbolAddress((void**)&zm2, g_zm2);
    cudaGetSymbolAddress((void**)&su1, g_su1);
    cudaGetSymbolAddress((void**)&su2, g_su2);
    cudaGetSymbolAddress((void**)&sm1, g_sm1);
    cudaGetSymbolAddress((void**)&sm2, g_sm2);
    cudaGetSymbolAddress((void**)&wa1, g_wa1);
    cudaGetSymbolAddress((void**)&wa2, g_wa2);
    cudaGetSymbolAddress((void**)&wa3, g_wa3);
    cudaGetSymbolAddress((void**)&wa4, g_wa4);
    cudaGetSymbolAddress((void**)&rp_um, g_rp_um);
    cudaGetSymbolAddress((void**)&rp_mu, g_rp_mu);
    cudaGetSymbolAddress((void**)&csr_um, g_csr_um);
    cudaGetSymbolAddress((void**)&csr_mu, g_csr_mu);
    cudaGetSymbolAddress((void**)&cnt_um, g_cnt_um);
    cudaGetSymbolAddress((void**)&cnt_mu, g_cnt_mu);
    cudaGetSymbolAddress((void**)&bsum, g_bsum);

    const int TB = 256;
    const int nb_um = ceil_div(NM, 1024), nb_mu = ceil_div(NU, 1024);

    // ================= CSR build (both graphs, once) =================
    cudaMemsetAsync(cnt_um, 0, NM * sizeof(int));
    cudaMemsetAsync(cnt_mu, 0, NU * sizeof(int));
    hist2_k<<<ceil_div(E, TB), TB>>>(um_dst, mu_dst, cnt_um, cnt_mu, E);
    blk_reduce_k<<<nb_um, 256>>>(cnt_um, bsum, NM);
    scan_bsum_k<<<1, 32>>>(bsum, nb_um);
    blk_scan_k<<<nb_um, 256>>>(cnt_um, bsum, rp_um, NM, E);
    blk_reduce_k<<<nb_mu, 256>>>(cnt_mu, bsum, NU);
    scan_bsum_k<<<1, 32>>>(bsum, nb_mu);
    blk_scan_k<<<nb_mu, 256>>>(cnt_mu, bsum, rp_mu, NU, E);
    cudaMemsetAsync(cnt_um, 0, NM * sizeof(int));
    cudaMemsetAsync(cnt_mu, 0, NU * sizeof(int));
    scatter2_k<<<ceil_div(E, TB), TB>>>(um_src, um_dst, rp_um, cnt_um, csr_um,
                                        mu_src, mu_dst, rp_mu, cnt_mu, csr_mu, E);

    // ================= layer 1 =================
    fold_k<<<ceil_div(FU * H1, TB), TB>>>(w1um_s, a1um_s, wa1, FU, H1, C1);  // es(xu) for um
    fold_k<<<ceil_div(FU * H1, TB), TB>>>(w1mu_d, a1mu_d, wa2, FU, H1, C1);  // ed(xu) for mu
    fold_k<<<ceil_div(FM * H1, TB), TB>>>(w1um_d, a1um_d, wa3, FM, H1, C1);  // ed(xm) for um
    fold_k<<<ceil_div(FM * H1, TB), TB>>>(w1mu_s, a1mu_s, wa4, FM, H1, C1);  // es(xm) for mu
    scores2_k<FU, H1><<<ceil_div(NU, 8), 256>>>(xu, wa1, wa2, su1, su2, NU);
    scores2_k<FM, H1><<<ceil_div(NM, 8), 256>>>(xm, wa3, wa4, sm1, sm2, NM);
    sgemm_k<<<dim3(1, ceil_div(NU, 128)), 256>>>(xu, FU, w1um_s, D1, hs1um, D1, NU, FU, nullptr, 0, 0);
    sgemm_k<<<dim3(1, ceil_div(NM, 128)), 256>>>(xm, FM, w1mu_s, D1, hs1mu, D1, NM, FM, nullptr, 0, 0);
    gat_aggr_k<H1, C1><<<ceil_div(NM, 8), 256>>>(rp_um, csr_um, su1, sm1, hs1um, b1um, zm, NM, 1);
    gat_aggr_k<H1, C1><<<ceil_div(NU, 8), 256>>>(rp_mu, csr_mu, sm2, su2, hs1mu, b1mu, zu, NU, 1);

    // ================= layer 2 =================
    fold_k<<<ceil_div(D1 * H2, TB), TB>>>(w2um_s, a2um_s, wa1, D1, H2, C2);  // es(zu) for um
    fold_k<<<ceil_div(D1 * H2, TB), TB>>>(w2mu_d, a2mu_d, wa2, D1, H2, C2);  // ed(zu) for mu
    fold_k<<<ceil_div(D1 * H2, TB), TB>>>(w2um_d, a2um_d, wa3, D1, H2, C2);  // ed(zm) for um
    fold_k<<<ceil_div(D1 * H2, TB), TB>>>(w2mu_s, a2mu_s, wa4, D1, H2, C2);  // es(zm) for mu
    scores2_k<D1, H2><<<ceil_div(NU, 8), 256>>>(zu, wa1, wa2, su1, su2, NU);
    scores2_k<D1, H2><<<ceil_div(NM, 8), 256>>>(zm, wa3, wa4, sm1, sm2, NM);
    // um: aggregate-first over zu, then block-diagonal GEMM + bias
    gat_aggr_pre4_k<<<ceil_div(NM, 8), 256>>>(rp_um, csr_um, su1, sm1, zu, agg, NM);
    sgemm_k<<<dim3(4, ceil_div(NM, 128)), 256>>>(agg, D2, w2um_s, D2, zm2, D2, NM, D1, b2um, 0, 1);
    // mu: GEMM-first over zm, then fused aggregation (+bias)
    sgemm_k<<<dim3(4, ceil_div(NM, 128)), 256>>>(zm, D1, w2mu_s, D2, hs2mu, D2, NM, D1, nullptr, 0, 0);
    gat_aggr_k<H2, C2><<<ceil_div(NU, 8), 256>>>(rp_mu, csr_mu, sm2, su2, hs2mu, b2mu, zu2, NU, 0);

    // ================= decoder =================
    dec_gemm_k<<<ceil_div(EL, 128), 256>>>(zu2, zm2, lab_u, lab_m, dw1, db1, dw2, db2, out, EL);
}